// round 5
// baseline (speedup 1.0000x reference)
#include <cuda_runtime.h>
#include <math.h>

#define LSTEPS 24
#define NN 16384
#define LN (LSTEPS*NN)
#define HH 128
#define G4 512
#define KK 264
#define D_OP 16
#define D_ATTR 56
#define D_FILT 74
#define D_OUTP 32

// ---------------- device scratch (static, no allocations) ----------------
__device__ float g_WT[KK*G4];          // transposed [Wih|Whh] : [k][j]
__device__ float g_bcomb[G4];          // bih + bhh
__device__ float g_weff[HH];           // W2 @ W1 collapsed head
__device__ float g_beff[1];
__device__ float g_af[(size_t)LN*32];  // leaky(filter@Wf^T+bf), pre-BN
__device__ float g_ao[(size_t)LN*32];  // leaky(output@Wo^T+bo), pre-BN
__device__ float g_partial[128*1024];  // BN partial sums [qty*32+feat][block]
__device__ float g_aff[4][32];         // scale_f, shift_f, scale_o, shift_o
__device__ float g_h[2][(size_t)NN*HH];
__device__ float g_c[2][(size_t)NN*HH];

__device__ __forceinline__ float sigf(float x){ return 1.f/(1.f+__expf(-x)); }

// ---------------- prologue: weight transpose + head collapse ----------------
__global__ void prep_kernel(const float* __restrict__ Wih, const float* __restrict__ Whh,
                            const float* __restrict__ bih, const float* __restrict__ bhh,
                            const float* __restrict__ W1,  const float* __restrict__ b1,
                            const float* __restrict__ W2,  const float* __restrict__ b2){
    int k = blockIdx.x, j = threadIdx.x;
    g_WT[k*G4 + j] = (k < 136) ? Wih[j*136 + k] : Whh[j*HH + (k-136)];
    if (k == 0) g_bcomb[j] = bih[j] + bhh[j];
    if (k == 1 && j < HH){
        float s = 0.f;
        #pragma unroll
        for (int t = 0; t < 20; t++) s += W2[t] * W1[t*HH + j];
        g_weff[j] = s;
    }
    if (k == 1 && j == HH){
        float s = b2[0];
        #pragma unroll
        for (int t = 0; t < 20; t++) s += W2[t] * b1[t];
        g_beff[0] = s;
    }
}

// ---------------- fd/od projections + deterministic BN partials ----------------
__global__ void __launch_bounds__(256) fdod_kernel(
        const float* __restrict__ filt, const float* __restrict__ outp,
        const float* __restrict__ Wf, const float* __restrict__ bf,
        const float* __restrict__ Wo, const float* __restrict__ bo){
    __shared__ float sWf[32][76];
    __shared__ float sWo[32][32];
    __shared__ float sx[8][76];
    __shared__ float so[8][32];
    __shared__ float sred[4][8][32];
    int tid = threadIdx.x;
    int j = tid & 31, r = tid >> 5;

    for (int idx = tid; idx < 32*76; idx += 256){
        int jj = idx/76, kk = idx%76;
        sWf[jj][kk] = (kk < 74) ? Wf[jj*74 + kk] : 0.f;
    }
    for (int idx = tid; idx < 32*32; idx += 256) sWo[idx>>5][idx&31] = Wo[idx];
    float bfj = bf[j], boj = bo[j];
    __syncthreads();

    float s0=0.f, s1=0.f, s2=0.f, s3=0.f;
    int base = blockIdx.x * 384;   // 1024 blocks * 384 rows = 393216
    for (int it = 0; it < 48; ++it){
        int row0 = base + it*8;
        __syncthreads();
        for (int idx = tid; idx < 8*76; idx += 256){
            int rr = idx/76, kk = idx%76;
            sx[rr][kk] = (kk < 74) ? filt[(size_t)(row0+rr)*74 + kk] : 0.f;
        }
        { int idx = tid; so[idx>>5][idx&31] = outp[(size_t)row0*32 + idx]; }
        __syncthreads();

        const float4* wf4 = (const float4*)sWf[j];
        const float4* x4  = (const float4*)sx[r];
        float af = bfj;
        #pragma unroll
        for (int q = 0; q < 19; q++){
            float4 w = wf4[q], x = x4[q];
            af += w.x*x.x; af += w.y*x.y; af += w.z*x.z; af += w.w*x.w;
        }
        const float4* wo4 = (const float4*)sWo[j];
        const float4* o4  = (const float4*)so[r];
        float ao = boj;
        #pragma unroll
        for (int q = 0; q < 8; q++){
            float4 w = wo4[q], x = o4[q];
            ao += w.x*x.x; ao += w.y*x.y; ao += w.z*x.z; ao += w.w*x.w;
        }
        af = af > 0.f ? af : 0.01f*af;
        ao = ao > 0.f ? ao : 0.01f*ao;
        size_t row = (size_t)row0 + r;
        g_af[row*32 + j] = af;
        g_ao[row*32 + j] = ao;
        s0 += af; s1 += af*af; s2 += ao; s3 += ao*ao;
    }
    __syncthreads();
    sred[0][r][j] = s0; sred[1][r][j] = s1; sred[2][r][j] = s2; sred[3][r][j] = s3;
    __syncthreads();
    if (tid < 128){
        int q = tid >> 5, jj = tid & 31;
        float s = 0.f;
        #pragma unroll
        for (int rr = 0; rr < 8; rr++) s += sred[q][rr][jj];
        g_partial[tid*1024 + blockIdx.x] = s;
    }
}

// ---------------- BN finalize (deterministic, fp64 reduce) ----------------
__global__ void bn_kernel(const float* __restrict__ g1, const float* __restrict__ beta1,
                          const float* __restrict__ g2, const float* __restrict__ beta2){
    __shared__ double dsum[128];
    int tid = threadIdx.x;
    double s = 0.0;
    const float* p = &g_partial[tid*1024];
    for (int b = 0; b < 1024; b++) s += (double)p[b];
    dsum[tid] = s;
    __syncthreads();
    if (tid < 32){
        double m = dsum[tid] / (double)LN;
        double v = dsum[32+tid] / (double)LN - m*m;
        float sc = g1[tid] * (float)(1.0 / sqrt(v + 1e-5));
        g_aff[0][tid] = sc;
        g_aff[1][tid] = beta1[tid] - (float)m * sc;
    } else if (tid < 64){
        int jj = tid - 32;
        double m = dsum[64+jj] / (double)LN;
        double v = dsum[96+jj] / (double)LN - m*m;
        float sc = g2[jj] * (float)(1.0 / sqrt(v + 1e-5));
        g_aff[2][jj] = sc;
        g_aff[3][jj] = beta2[jj] - (float)m * sc;
    }
}

// ---------------- one LSTM step: gather + fused GEMM + activations ----------------
__global__ void __launch_bounds__(512) step_kernel(
        int l,
        const float* __restrict__ op, const float* __restrict__ attr,
        const int* __restrict__ mapping,
        const float* __restrict__ h_in, const float* __restrict__ c_in,
        float* __restrict__ h_out, float* __restrict__ c_out){
    extern __shared__ float sm[];
    float* xs  = sm;                 // [KK][16]  x-tile, k-major for LDS.128 broadcast
    float* gcs = sm + KK*16;         // [16][HH]  gathered c
    float* gts = gcs + 16*HH;        // [16][G4]  gates staging
    __shared__ int   smap[16][2];
    __shared__ float saff[4][32];

    int tid = threadIdx.x;
    int node0 = blockIdx.x * 16;

    if (tid < 32) smap[tid>>1][tid&1] = mapping[((size_t)l*NN + node0 + (tid>>1))*2 + (tid&1)];
    if (tid >= 32 && tid < 160) ((float*)saff)[tid-32] = ((const float*)g_aff)[tid-32];
    __syncthreads();

    size_t rowbase = (size_t)l*NN + node0;
    for (int t = tid; t < KK*16; t += 512){
        int k = t >> 4, i = t & 15;
        size_t n = rowbase + i;
        float v;
        if (k < 16)        v = op[n*D_OP + k];
        else if (k < 72)   v = attr[n*D_ATTR + (k-16)];
        else if (k < 104){ int f = k-72;  v = g_af[n*32 + f]*saff[0][f] + saff[1][f]; }
        else if (k < 136){ int f = k-104; v = g_ao[n*32 + f]*saff[2][f] + saff[3][f]; }
        else {
            int u = k - 136;
            int m0 = smap[i][0], m1 = smap[i][1];
            float a = 0.f;
            if (m0) a += h_in[(size_t)(m0-1)*HH + u];
            if (m1) a += h_in[(size_t)(m1-1)*HH + u];
            v = 0.5f * a;
        }
        xs[k*16 + i] = v;
    }
    for (int t = tid; t < 16*HH; t += 512){
        int i = t >> 7, u = t & 127;
        int m0 = smap[i][0], m1 = smap[i][1];
        float a = 0.f;
        if (m0) a += c_in[(size_t)(m0-1)*HH + u];
        if (m1) a += c_in[(size_t)(m1-1)*HH + u];
        gcs[t] = 0.5f * a;
    }
    __syncthreads();

    // GEMM: 512 threads, thread j owns gate j for 16 nodes
    {
        int j = tid;
        float b = g_bcomb[j];
        float acc[16];
        #pragma unroll
        for (int i = 0; i < 16; i++) acc[i] = b;
        const float4* xs4 = (const float4*)xs;
        #pragma unroll 4
        for (int k = 0; k < KK; k++){
            float w = g_WT[k*G4 + j];                 // coalesced, L2-resident
            float4 x0 = xs4[k*4+0], x1 = xs4[k*4+1];  // broadcast LDS.128
            float4 x2 = xs4[k*4+2], x3 = xs4[k*4+3];
            acc[0]  += w*x0.x; acc[1]  += w*x0.y; acc[2]  += w*x0.z; acc[3]  += w*x0.w;
            acc[4]  += w*x1.x; acc[5]  += w*x1.y; acc[6]  += w*x1.z; acc[7]  += w*x1.w;
            acc[8]  += w*x2.x; acc[9]  += w*x2.y; acc[10] += w*x2.z; acc[11] += w*x2.w;
            acc[12] += w*x3.x; acc[13] += w*x3.y; acc[14] += w*x3.z; acc[15] += w*x3.w;
        }
        #pragma unroll
        for (int i = 0; i < 16; i++) gts[i*G4 + j] = acc[i];
    }
    __syncthreads();

    for (int t = tid; t < 16*HH; t += 512){
        int i = t >> 7, u = t & 127;
        float gi = gts[i*G4 + u];
        float gf = gts[i*G4 + u + 128];
        float gg = gts[i*G4 + u + 256];
        float go = gts[i*G4 + u + 384];
        float gc = gcs[t];
        float c  = sigf(gf)*gc + sigf(gi)*tanhf(gg);
        float h  = sigf(go)*tanhf(c);
        size_t n = (size_t)(node0 + i);
        c_out[n*HH + u] = c;
        h_out[n*HH + u] = h;
    }
}

// ---------------- head: out = sigmoid(h . weff + beff), one warp per node ----------------
__global__ void head_kernel(const float* __restrict__ h, float* __restrict__ out, int nb){
    int warp = (blockIdx.x * blockDim.x + threadIdx.x) >> 5;
    int lane = threadIdx.x & 31;
    if (warp >= nb) return;
    const float* hr = h + (size_t)warp * HH;
    float s = hr[lane]      * g_weff[lane]
            + hr[lane+32]   * g_weff[lane+32]
            + hr[lane+64]   * g_weff[lane+64]
            + hr[lane+96]   * g_weff[lane+96];
    #pragma unroll
    for (int o = 16; o > 0; o >>= 1) s += __shfl_down_sync(0xffffffffu, s, o);
    if (lane == 0) out[warp] = 1.f/(1.f + __expf(-(s + g_beff[0])));
}

// ---------------- launch ----------------
extern "C" void kernel_launch(void* const* d_in, const int* in_sizes, int n_in,
                              void* d_out, int out_size){
    // batch_size may or may not appear as a 1-element input at index 5
    int off = (n_in >= 6 && in_sizes[5] == 1) ? 1 : 0;
    const float* op    = (const float*)d_in[0];
    const float* attr  = (const float*)d_in[1];
    const float* filt  = (const float*)d_in[2];
    const float* outp  = (const float*)d_in[3];
    const int*   mapping = (const int*)d_in[4];
    const float* Wf  = (const float*)d_in[5+off];
    const float* bf  = (const float*)d_in[6+off];
    const float* Wo  = (const float*)d_in[7+off];
    const float* bo  = (const float*)d_in[8+off];
    const float* g1  = (const float*)d_in[9+off];
    const float* beta1 = (const float*)d_in[10+off];
    const float* g2  = (const float*)d_in[11+off];
    const float* beta2 = (const float*)d_in[12+off];
    const float* Wih = (const float*)d_in[13+off];
    const float* Whh = (const float*)d_in[14+off];
    const float* bih = (const float*)d_in[15+off];
    const float* bhh = (const float*)d_in[16+off];
    const float* W1  = (const float*)d_in[17+off];
    const float* b1  = (const float*)d_in[18+off];
    const float* W2  = (const float*)d_in[19+off];
    const float* b2  = (const float*)d_in[20+off];

    void* hptr; void* cptr;
    cudaGetSymbolAddress(&hptr, g_h);
    cudaGetSymbolAddress(&cptr, g_c);
    cudaMemsetAsync(hptr, 0, sizeof(float)*(size_t)NN*HH, 0);  // zero initial h
    cudaMemsetAsync(cptr, 0, sizeof(float)*(size_t)NN*HH, 0);  // zero initial c

    prep_kernel<<<KK, G4>>>(Wih, Whh, bih, bhh, W1, b1, W2, b2);
    fdod_kernel<<<1024, 256>>>(filt, outp, Wf, bf, Wo, bo);
    bn_kernel<<<1, 128>>>(g1, beta1, g2, beta2);

    const int smem_bytes = (KK*16 + 16*HH + 16*G4) * (int)sizeof(float);  // 57856
    cudaFuncSetAttribute(step_kernel, cudaFuncAttributeMaxDynamicSharedMemorySize, smem_bytes);

    float* hbuf = (float*)hptr;
    float* cbuf = (float*)cptr;
    for (int t = 0; t < LSTEPS; t++){
        int l = LSTEPS - 1 - t;
        const float* hi = hbuf + (size_t)(t & 1) * NN * HH;
        const float* ci = cbuf + (size_t)(t & 1) * NN * HH;
        float* ho = hbuf + (size_t)((t & 1) ^ 1) * NN * HH;
        float* co = cbuf + (size_t)((t & 1) ^ 1) * NN * HH;
        step_kernel<<<NN/16, 512, smem_bytes>>>(l, op, attr, mapping, hi, ci, ho, co);
    }
    // after 24 steps (even count), final h sits in buffer 0
    head_kernel<<<(out_size + 7) / 8, 256>>>(hbuf, (float*)d_out, out_size);
}